// round 4
// baseline (speedup 1.0000x reference)
#include <cuda_runtime.h>

// Problem constants
#define BB 2
#define BN 4096
#define PARTS 8
#define CPART (BN / PARTS)       // 512 columns per partition
#define TPB 128                  // threads per block
#define RROWS 2                  // rows per thread
#define RPB (TPB * RROWS)        // 256 rows per block
#define ROWTILES (BN / RPB)      // 16
#define LOG2E 1.4426950408889634f
#define LN2 0.6931471805599453f

// Scratch (allocation-free)
__device__ float g_x2[BB * BN];
__device__ float g_y2[BB * BN];
__device__ float g_ax[BB * BN];
__device__ float g_by[BB * BN];
__device__ float g_bx[BB * BN];
__device__ float g_ay[BB * BN];
__device__ float g_pm[4 * BB * PARTS * BN];
__device__ float g_ps[4 * BB * PARTS * BN];

typedef unsigned long long ull;

__device__ __forceinline__ float ex2f(float x) {
    float r;
    asm("ex2.approx.f32 %0, %1;" : "=f"(r) : "f"(x));
    return r;
}
__device__ __forceinline__ float lg2f(float x) {
    float r;
    asm("lg2.approx.f32 %0, %1;" : "=f"(r) : "f"(x));
    return r;
}
__device__ __forceinline__ ull fma2(ull a, ull b, ull c) {
    ull d;
    asm("fma.rn.f32x2 %0, %1, %2, %3;" : "=l"(d) : "l"(a), "l"(b), "l"(c));
    return d;
}
__device__ __forceinline__ ull add2(ull a, ull b) {
    ull d;
    asm("add.rn.f32x2 %0, %1, %2;" : "=l"(d) : "l"(a), "l"(b));
    return d;
}
__device__ __forceinline__ ull fpack(float lo, float hi) {
    ull r;
    asm("mov.b64 %0, {%1, %2};" : "=l"(r) : "f"(lo), "f"(hi));
    return r;
}
__device__ __forceinline__ float flo(ull v) {
    float lo, hi;
    asm("mov.b64 {%0, %1}, %2;" : "=f"(lo), "=f"(hi) : "l"(v));
    return lo;
}
__device__ __forceinline__ float fhi(ull v) {
    float lo, hi;
    asm("mov.b64 {%0, %1}, %2;" : "=f"(lo), "=f"(hi) : "l"(v));
    return hi;
}

// Precompute 0.5*||p||^2 for both point sets
__global__ void sqnorm_kernel(const float* __restrict__ X, const float* __restrict__ Y) {
    int i = blockIdx.x * blockDim.x + threadIdx.x;
    if (i < BB * BN) {
        float a = X[3 * i], b = X[3 * i + 1], c = X[3 * i + 2];
        g_x2[i] = 0.5f * (a * a + b * b + c * c);
        a = Y[3 * i]; b = Y[3 * i + 1]; c = Y[3 * i + 2];
        g_y2[i] = 0.5f * (a * a + b * b + c * c);
    }
}

// One stage: 4 softmins. Log2-domain online LSE over column partitions.
// v_ij = g_j + (x_i * log2e/eps) . y_j,  g_j = -12 + (dual_j - 0.5|y_j|^2) * log2e/eps
// Packed f32x2: each thread carries TWO rows; shared columns stored duplicated so
// LDS.128 yields (y,y) packed operand pairs directly.
// Tasks: t0: C_xx h=a_x | t1: C_yy h=b_y | t2: C_xy h=a_y -> b_x | t3: C_yx h=b_x -> a_y
__global__ __launch_bounds__(TPB) void softmin_kernel(const float* __restrict__ X,
                                                      const float* __restrict__ Y,
                                                      float eps, float dualScale) {
    __shared__ ulonglong2 shA[CPART];   // (y0,y0),(y1,y1)
    __shared__ ulonglong2 shB[CPART];   // (y2,y2),(g , g)

    int bi = blockIdx.x;
    int part    = bi & (PARTS - 1);
    int rowTile = (bi >> 3) & (ROWTILES - 1);
    int b       = (bi >> 7) & (BB - 1);
    int task    = bi >> 8;

    const float* rowP = (task == 0 || task == 2) ? X : Y;
    const float* colP = (task == 0 || task == 3) ? X : Y;
    const float* colQ = (task == 0 || task == 3) ? g_x2 : g_y2;
    const float* colD = (task == 0) ? g_ax : (task == 1) ? g_by : (task == 2) ? g_ay : g_bx;

    const float sLe = LOG2E / eps;
    int tid = threadIdx.x;

    for (int jj = tid; jj < CPART; jj += TPB) {
        int j  = part * CPART + jj;
        int gj = b * BN + j;
        float y0 = colP[3 * gj], y1 = colP[3 * gj + 1], y2 = colP[3 * gj + 2];
        float g  = -12.0f + (colD[gj] * dualScale - colQ[gj]) * sLe;
        ulonglong2 A, B;
        A.x = fpack(y0, y0); A.y = fpack(y1, y1);
        B.x = fpack(y2, y2); B.y = fpack(g, g);
        shA[jj] = A;
        shB[jj] = B;
    }
    __syncthreads();

    int r0 = rowTile * RPB + tid;        // row for lo lane
    int r1 = r0 + TPB;                   // row for hi lane
    int g0 = b * BN + r0;
    int g1 = b * BN + r1;
    ull X0 = fpack(rowP[3 * g0] * sLe,     rowP[3 * g1] * sLe);
    ull X1 = fpack(rowP[3 * g0 + 1] * sLe, rowP[3 * g1 + 1] * sLe);
    ull X2 = fpack(rowP[3 * g0 + 2] * sLe, rowP[3 * g1 + 2] * sLe);

    float m0 = -3.0e38f, m1 = -3.0e38f;
    float s00 = 0.f, s01 = 0.f, s10 = 0.f, s11 = 0.f;

    for (int jj = 0; jj < CPART; jj += 8) {
        ull v[8];
#pragma unroll
        for (int k = 0; k < 8; k++) {
            ulonglong2 A = shA[jj + k];
            ulonglong2 B = shB[jj + k];
            ull t = fma2(X2, B.x, B.y);
            t = fma2(X1, A.y, t);
            v[k] = fma2(X0, A.x, t);
        }
        // chunk max per row (scalar FMNMX tree on packed halves)
        float c0 = fmaxf(fmaxf(fmaxf(flo(v[0]), flo(v[1])), fmaxf(flo(v[2]), flo(v[3]))),
                         fmaxf(fmaxf(flo(v[4]), flo(v[5])), fmaxf(flo(v[6]), flo(v[7]))));
        float c1 = fmaxf(fmaxf(fmaxf(fhi(v[0]), fhi(v[1])), fmaxf(fhi(v[2]), fhi(v[3]))),
                         fmaxf(fmaxf(fhi(v[4]), fhi(v[5])), fmaxf(fhi(v[6]), fhi(v[7]))));
        if (c0 > m0) {                 // skipped path multiplies by exactly 1.0 -> identical
            float sc = ex2f(m0 - c0);
            s00 *= sc; s01 *= sc; m0 = c0;
        }
        if (c1 > m1) {
            float sc = ex2f(m1 - c1);
            s10 *= sc; s11 *= sc; m1 = c1;
        }
        ull nm = fpack(-m0, -m1);
#pragma unroll
        for (int k = 0; k < 8; k += 2) {
            ull e0 = add2(v[k], nm);
            ull e1 = add2(v[k + 1], nm);
            s00 += ex2f(flo(e0)); s10 += ex2f(fhi(e0));
            s01 += ex2f(flo(e1)); s11 += ex2f(fhi(e1));
        }
    }

    int base = ((task * BB + b) * PARTS + part) * BN;
    g_pm[base + r0] = m0;
    g_ps[base + r0] = s00 + s01;
    g_pm[base + r1] = m1;
    g_ps[base + r1] = s10 + s11;
}

// Combine partition partials -> softmin value; optionally average with old dual (in place).
__global__ void merge_kernel(float eps, int avg) {
    int idx = blockIdx.x * blockDim.x + threadIdx.x;
    if (idx >= 4 * BB * BN) return;
    int task = idx / (BB * BN);
    int rem  = idx - task * (BB * BN);
    int b    = rem / BN;
    int r    = rem - b * BN;

    const float* rowQ = (task == 0 || task == 2) ? g_x2 : g_y2;
    float* outA = (task == 0) ? g_ax : (task == 1) ? g_by : (task == 2) ? g_bx : g_ay;

    int base = (task * BB + b) * (PARTS * BN) + r;
    float M = -3.0e38f;
#pragma unroll
    for (int p = 0; p < PARTS; p++) M = fmaxf(M, g_pm[base + p * BN]);
    float s = 0.f;
#pragma unroll
    for (int p = 0; p < PARTS; p++)
        s = fmaf(g_ps[base + p * BN], ex2f(g_pm[base + p * BN] - M), s);

    float sLe = LOG2E / eps;
    float ri  = -rowQ[rem] * sLe;
    float val = -eps * LN2 * (ri + M + lg2f(s));
    if (avg) val = 0.5f * (outA[rem] + val);
    outA[rem] = val;
}

// F = sum_b [ (1/N) sum_i (b_x - a_x) + (1/M) sum_j (a_y - b_y) ]
__global__ void reduce_kernel(float* __restrict__ out) {
    __shared__ float sh[32];
    int tid = threadIdx.x;
    float acc = 0.f;
    for (int i = tid; i < BB * BN; i += blockDim.x)
        acc += (g_bx[i] - g_ax[i]) + (g_ay[i] - g_by[i]);
    acc *= (1.0f / BN);
#pragma unroll
    for (int o = 16; o; o >>= 1) acc += __shfl_down_sync(0xFFFFFFFFu, acc, o);
    if ((tid & 31) == 0) sh[tid >> 5] = acc;
    __syncthreads();
    if (tid < 32) {
        float v = (tid < (int)(blockDim.x >> 5)) ? sh[tid] : 0.f;
#pragma unroll
        for (int o = 16; o; o >>= 1) v += __shfl_down_sync(0xFFFFFFFFu, v, o);
        if (tid == 0) out[0] = v;
    }
}

extern "C" void kernel_launch(void* const* d_in, const int* in_sizes, int n_in,
                              void* d_out, int out_size) {
    const float* X = (const float*)d_in[0];   // true_data
    const float* Y = (const float*)d_in[1];   // particles
    float* out = (float*)d_out;

    sqnorm_kernel<<<(BB * BN + 255) / 256, 256>>>(X, Y);

    // geomloss eps schedule: [16] + [16,4,1,0.25,0.0625,0.015625,0.00390625] + [0.0025]
    const float epsList[9] = {16.f, 16.f, 4.f, 1.f, 0.25f, 0.0625f,
                              0.015625f, 0.00390625f, 0.0025f};

    const int gridSoft = 4 * BB * ROWTILES * PARTS;   // 1024 blocks
    const int gridMerge = (4 * BB * BN) / 256;        // 128 blocks

    // init (dual term off, assignment)
    softmin_kernel<<<gridSoft, TPB>>>(X, Y, 16.f, 0.f);
    merge_kernel<<<gridMerge, 256>>>(16.f, 0);

    // eps-scaling loop (symmetrized, averaged updates)
    for (int e = 0; e < 9; e++) {
        softmin_kernel<<<gridSoft, TPB>>>(X, Y, epsList[e], 1.f);
        merge_kernel<<<gridMerge, 256>>>(epsList[e], 1);
    }

    // final extrapolation at blur^2 (assignment, no averaging)
    softmin_kernel<<<gridSoft, TPB>>>(X, Y, 0.0025f, 1.f);
    merge_kernel<<<gridMerge, 256>>>(0.0025f, 0);

    reduce_kernel<<<1, 256>>>(out);
}

// round 5
// speedup vs baseline: 1.0569x; 1.0569x over previous
#include <cuda_runtime.h>

// Problem constants
#define BB 2
#define BN 4096
#define PARTS 16
#define CPART (BN / PARTS)       // 256 columns per partition
#define TPB 256                  // threads per block
#define RROWS 2                  // rows per thread (packed f32x2)
#define RPB (TPB * RROWS)        // 512 rows per block
#define ROWTILES (BN / RPB)      // 8
#define LOG2E 1.4426950408889634f
#define LN2 0.6931471805599453f

// Scratch (allocation-free)
__device__ float g_x2[BB * BN];
__device__ float g_y2[BB * BN];
__device__ float g_ax[BB * BN];
__device__ float g_by[BB * BN];
__device__ float g_bx[BB * BN];
__device__ float g_ay[BB * BN];
__device__ float g_pm[4 * BB * PARTS * BN];
__device__ float g_ps[4 * BB * PARTS * BN];

typedef unsigned long long ull;

__device__ __forceinline__ float ex2f(float x) {
    float r;
    asm("ex2.approx.f32 %0, %1;" : "=f"(r) : "f"(x));
    return r;
}
__device__ __forceinline__ float lg2f(float x) {
    float r;
    asm("lg2.approx.f32 %0, %1;" : "=f"(r) : "f"(x));
    return r;
}
__device__ __forceinline__ ull fma2(ull a, ull b, ull c) {
    ull d;
    asm("fma.rn.f32x2 %0, %1, %2, %3;" : "=l"(d) : "l"(a), "l"(b), "l"(c));
    return d;
}
__device__ __forceinline__ ull add2(ull a, ull b) {
    ull d;
    asm("add.rn.f32x2 %0, %1, %2;" : "=l"(d) : "l"(a), "l"(b));
    return d;
}
__device__ __forceinline__ ull fpack(float lo, float hi) {
    ull r;
    asm("mov.b64 %0, {%1, %2};" : "=l"(r) : "f"(lo), "f"(hi));
    return r;
}
__device__ __forceinline__ float flo(ull v) {
    float lo, hi;
    asm("mov.b64 {%0, %1}, %2;" : "=f"(lo), "=f"(hi) : "l"(v));
    return lo;
}
__device__ __forceinline__ float fhi(ull v) {
    float lo, hi;
    asm("mov.b64 {%0, %1}, %2;" : "=f"(lo), "=f"(hi) : "l"(v));
    return hi;
}

// Precompute 0.5*||p||^2 for both point sets
__global__ void sqnorm_kernel(const float* __restrict__ X, const float* __restrict__ Y) {
    int i = blockIdx.x * blockDim.x + threadIdx.x;
    if (i < BB * BN) {
        float a = X[3 * i], b = X[3 * i + 1], c = X[3 * i + 2];
        g_x2[i] = 0.5f * (a * a + b * b + c * c);
        a = Y[3 * i]; b = Y[3 * i + 1]; c = Y[3 * i + 2];
        g_y2[i] = 0.5f * (a * a + b * b + c * c);
    }
}

// One stage: 4 softmins. Log2-domain online LSE over column partitions.
// v_ij = g_j + (x_i * log2e/eps) . y_j,  g_j = -12 + (dual_j - 0.5|y_j|^2) * log2e/eps
// Packed f32x2: each thread carries TWO rows; shared columns stored duplicated so
// LDS.128 yields (y,y) packed operand pairs directly. Branchless rescale (no BSSY).
// Tasks: t0: C_xx h=a_x | t1: C_yy h=b_y | t2: C_xy h=a_y -> b_x | t3: C_yx h=b_x -> a_y
__global__ __launch_bounds__(TPB) void softmin_kernel(const float* __restrict__ X,
                                                      const float* __restrict__ Y,
                                                      float eps, float dualScale) {
    __shared__ ulonglong2 shA[CPART];   // (y0,y0),(y1,y1)
    __shared__ ulonglong2 shB[CPART];   // (y2,y2),(g , g)

    int bi = blockIdx.x;
    int part    = bi & (PARTS - 1);
    int rowTile = (bi >> 4) & (ROWTILES - 1);
    int b       = (bi >> 7) & (BB - 1);
    int task    = bi >> 8;

    const float* rowP = (task == 0 || task == 2) ? X : Y;
    const float* colP = (task == 0 || task == 3) ? X : Y;
    const float* colQ = (task == 0 || task == 3) ? g_x2 : g_y2;
    const float* colD = (task == 0) ? g_ax : (task == 1) ? g_by : (task == 2) ? g_ay : g_bx;

    const float sLe = LOG2E / eps;
    int tid = threadIdx.x;

    for (int jj = tid; jj < CPART; jj += TPB) {
        int j  = part * CPART + jj;
        int gj = b * BN + j;
        float y0 = colP[3 * gj], y1 = colP[3 * gj + 1], y2 = colP[3 * gj + 2];
        float g  = -12.0f + (colD[gj] * dualScale - colQ[gj]) * sLe;
        ulonglong2 A, B;
        A.x = fpack(y0, y0); A.y = fpack(y1, y1);
        B.x = fpack(y2, y2); B.y = fpack(g, g);
        shA[jj] = A;
        shB[jj] = B;
    }
    __syncthreads();

    int r0 = rowTile * RPB + tid;        // row for lo lane
    int r1 = r0 + TPB;                   // row for hi lane
    int g0 = b * BN + r0;
    int g1 = b * BN + r1;
    ull X0 = fpack(rowP[3 * g0] * sLe,     rowP[3 * g1] * sLe);
    ull X1 = fpack(rowP[3 * g0 + 1] * sLe, rowP[3 * g1 + 1] * sLe);
    ull X2 = fpack(rowP[3 * g0 + 2] * sLe, rowP[3 * g1 + 2] * sLe);

    float m0 = -3.0e38f, m1 = -3.0e38f;
    float s00 = 0.f, s01 = 0.f, s10 = 0.f, s11 = 0.f;

    for (int jj = 0; jj < CPART; jj += 8) {
        ull v[8];
#pragma unroll
        for (int k = 0; k < 8; k++) {
            ulonglong2 A = shA[jj + k];
            ulonglong2 B = shB[jj + k];
            ull t = fma2(X2, B.x, B.y);
            t = fma2(X1, A.y, t);
            v[k] = fma2(X0, A.x, t);
        }
        // chunk max per row (scalar FMNMX tree on packed halves)
        float c0 = fmaxf(fmaxf(fmaxf(flo(v[0]), flo(v[1])), fmaxf(flo(v[2]), flo(v[3]))),
                         fmaxf(fmaxf(flo(v[4]), flo(v[5])), fmaxf(flo(v[6]), flo(v[7]))));
        float c1 = fmaxf(fmaxf(fmaxf(fhi(v[0]), fhi(v[1])), fmaxf(fhi(v[2]), fhi(v[3]))),
                         fmaxf(fmaxf(fhi(v[4]), fhi(v[5])), fmaxf(fhi(v[6]), fhi(v[7]))));
        // branchless rescale: sc == 1.0 exactly when max unchanged
        float mn0 = fmaxf(m0, c0);
        float mn1 = fmaxf(m1, c1);
        float sc0 = ex2f(m0 - mn0);
        float sc1 = ex2f(m1 - mn1);
        s00 *= sc0; s01 *= sc0; m0 = mn0;
        s10 *= sc1; s11 *= sc1; m1 = mn1;
        ull nm = fpack(-m0, -m1);
#pragma unroll
        for (int k = 0; k < 8; k += 2) {
            ull e0 = add2(v[k], nm);
            ull e1 = add2(v[k + 1], nm);
            s00 += ex2f(flo(e0)); s10 += ex2f(fhi(e0));
            s01 += ex2f(flo(e1)); s11 += ex2f(fhi(e1));
        }
    }

    int base = ((task * BB + b) * PARTS + part) * BN;
    g_pm[base + r0] = m0;
    g_ps[base + r0] = s00 + s01;
    g_pm[base + r1] = m1;
    g_ps[base + r1] = s10 + s11;
}

// Combine partition partials -> softmin value; optionally average with old dual (in place).
__global__ void merge_kernel(float eps, int avg) {
    int idx = blockIdx.x * blockDim.x + threadIdx.x;
    if (idx >= 4 * BB * BN) return;
    int task = idx / (BB * BN);
    int rem  = idx - task * (BB * BN);
    int b    = rem / BN;
    int r    = rem - b * BN;

    const float* rowQ = (task == 0 || task == 2) ? g_x2 : g_y2;
    float* outA = (task == 0) ? g_ax : (task == 1) ? g_by : (task == 2) ? g_bx : g_ay;

    int base = (task * BB + b) * (PARTS * BN) + r;
    float M = -3.0e38f;
#pragma unroll
    for (int p = 0; p < PARTS; p++) M = fmaxf(M, g_pm[base + p * BN]);
    float s = 0.f;
#pragma unroll
    for (int p = 0; p < PARTS; p++)
        s = fmaf(g_ps[base + p * BN], ex2f(g_pm[base + p * BN] - M), s);

    float sLe = LOG2E / eps;
    float ri  = -rowQ[rem] * sLe;
    float val = -eps * LN2 * (ri + M + lg2f(s));
    if (avg) val = 0.5f * (outA[rem] + val);
    outA[rem] = val;
}

// F = sum_b [ (1/N) sum_i (b_x - a_x) + (1/M) sum_j (a_y - b_y) ]
__global__ void reduce_kernel(float* __restrict__ out) {
    __shared__ float sh[32];
    int tid = threadIdx.x;
    float acc = 0.f;
    for (int i = tid; i < BB * BN; i += blockDim.x)
        acc += (g_bx[i] - g_ax[i]) + (g_ay[i] - g_by[i]);
    acc *= (1.0f / BN);
#pragma unroll
    for (int o = 16; o; o >>= 1) acc += __shfl_down_sync(0xFFFFFFFFu, acc, o);
    if ((tid & 31) == 0) sh[tid >> 5] = acc;
    __syncthreads();
    if (tid < 32) {
        float v = (tid < (int)(blockDim.x >> 5)) ? sh[tid] : 0.f;
#pragma unroll
        for (int o = 16; o; o >>= 1) v += __shfl_down_sync(0xFFFFFFFFu, v, o);
        if (tid == 0) out[0] = v;
    }
}

extern "C" void kernel_launch(void* const* d_in, const int* in_sizes, int n_in,
                              void* d_out, int out_size) {
    const float* X = (const float*)d_in[0];   // true_data
    const float* Y = (const float*)d_in[1];   // particles
    float* out = (float*)d_out;

    sqnorm_kernel<<<(BB * BN + 255) / 256, 256>>>(X, Y);

    // geomloss eps schedule: [16] + [16,4,1,0.25,0.0625,0.015625,0.00390625] + [0.0025]
    const float epsList[9] = {16.f, 16.f, 4.f, 1.f, 0.25f, 0.0625f,
                              0.015625f, 0.00390625f, 0.0025f};

    const int gridSoft = 4 * BB * ROWTILES * PARTS;   // 1024 blocks
    const int gridMerge = (4 * BB * BN) / 256;        // 128 blocks

    // init (dual term off, assignment)
    softmin_kernel<<<gridSoft, TPB>>>(X, Y, 16.f, 0.f);
    merge_kernel<<<gridMerge, 256>>>(16.f, 0);

    // eps-scaling loop (symmetrized, averaged updates)
    for (int e = 0; e < 9; e++) {
        softmin_kernel<<<gridSoft, TPB>>>(X, Y, epsList[e], 1.f);
        merge_kernel<<<gridMerge, 256>>>(epsList[e], 1);
    }

    // final extrapolation at blur^2 (assignment, no averaging)
    softmin_kernel<<<gridSoft, TPB>>>(X, Y, 0.0025f, 1.f);
    merge_kernel<<<gridMerge, 256>>>(0.0025f, 0);

    reduce_kernel<<<1, 256>>>(out);
}